// round 13
// baseline (speedup 1.0000x reference)
#include <cuda_runtime.h>
#include <math.h>
#include <stdint.h>

// Problem constants
#define Bn 64
#define Cn 60
#define Tn 4096
#define Jn 270
#define MMn 1024   // K*K = 32*32

// ---------------- device scratch ----------------
__device__ float g_cs[Cn * MMn];         // cos table [c][m]
__device__ float g_sn[Cn * MMn];         // sin table [c][m]
__device__ float g_apart[16 * 288 * 64]; // logit partials [ms][j(288)][c(64)]
__device__ float g_w[Jn * Cn];           // softmax weights [j][c]

__device__ __forceinline__ float tf32_rna(float v) {
    float r; asm("cvt.rna.tf32.f32 %0, %1;" : "=f"(r) : "f"(v)); return r;
}
__device__ __forceinline__ uint32_t smem_u32(const void* p) {
    uint32_t a;
    asm("{ .reg .u64 t; cvta.to.shared.u64 t, %1; cvt.u32.u64 %0, t; }" : "=r"(a) : "l"(p));
    return a;
}
__device__ __forceinline__ void cp16(uint32_t dst, const void* src) {
    asm volatile("cp.async.cg.shared.global [%0], [%1], 16;" :: "r"(dst), "l"(src));
}
#define CP_COMMIT() asm volatile("cp.async.commit_group;" ::: "memory")
#define CP_WAIT(n)  asm volatile("cp.async.wait_group %0;" :: "n"(n) : "memory")

// m16n8k8 tf32 mma: D += A(row,16x8) * B(col,8x8)
__device__ __forceinline__ void mma8(float* d, const uint32_t* a, const uint32_t* b) {
    asm volatile(
        "mma.sync.aligned.m16n8k8.row.col.f32.tf32.tf32.f32 "
        "{%0,%1,%2,%3}, {%4,%5,%6,%7}, {%8,%9}, {%0,%1,%2,%3};"
        : "+f"(d[0]), "+f"(d[1]), "+f"(d[2]), "+f"(d[3])
        : "r"(a[0]), "r"(a[1]), "r"(a[2]), "r"(a[3]), "r"(b[0]), "r"(b[1]));
}

// ---------------- Kernel A: trig tables ----------------
__global__ void k_tables(const float* __restrict__ loc) {
    int c = blockIdx.x;
    float x = loc[c * 2 + 0];
    float y = loc[c * 2 + 1];
    for (int m = threadIdx.x; m < MMn; m += blockDim.x) {
        int k = m >> 5, l = m & 31;
        float r = (float)k * x + (float)l * y;
        r -= rintf(r);
        float s, cv;
        sincospif(2.0f * r, &s, &cv);
        g_cs[c * MMn + m] = cv;
        g_sn[c * MMn + m] = s;
    }
}

// ---------------- Kernel B: logits GEMM (16 m-splits, single 64-m pass) ----------------
__global__ __launch_bounds__(256) void k_logits(const float* __restrict__ z_re,
                                                const float* __restrict__ z_im) {
    __shared__ float zr[32][65], zi[32][65], tc[32][65], ts[32][65];
    int j0 = blockIdx.x * 32;
    int c0 = blockIdx.y * 32;
    int m0 = blockIdx.z * 64;
    int tid = threadIdx.x;
    int tx = tid & 15, ty = tid >> 4;

    for (int i = tid; i < 2048; i += 256) {
        int rr = i >> 6, mm = i & 63;
        int gm = m0 + mm;
        int j = j0 + rr;
        float vr = 0.f, vi = 0.f;
        if (j < Jn) { vr = z_re[j * MMn + gm]; vi = z_im[j * MMn + gm]; }
        zr[rr][mm] = vr; zi[rr][mm] = vi;
        int c = c0 + rr;
        float vc = 0.f, vs = 0.f;
        if (c < Cn) { vc = g_cs[c * MMn + gm]; vs = g_sn[c * MMn + gm]; }
        tc[rr][mm] = vc; ts[rr][mm] = vs;
    }
    __syncthreads();

    float a00 = 0.f, a01 = 0.f, a10 = 0.f, a11 = 0.f;
    #pragma unroll 16
    for (int mm = 0; mm < 64; mm++) {
        float r0 = zr[ty][mm],      r1 = zr[ty + 16][mm];
        float i0 = zi[ty][mm],      i1 = zi[ty + 16][mm];
        float c0v = tc[tx][mm],     c1v = tc[tx + 16][mm];
        float s0v = ts[tx][mm],     s1v = ts[tx + 16][mm];
        a00 += r0 * c0v + i0 * s0v;
        a01 += r0 * c1v + i0 * s1v;
        a10 += r1 * c0v + i1 * s0v;
        a11 += r1 * c1v + i1 * s1v;
    }
    int ms = blockIdx.z;
    g_apart[(ms * 288 + j0 + ty)      * 64 + c0 + tx]      = a00;
    g_apart[(ms * 288 + j0 + ty)      * 64 + c0 + tx + 16] = a01;
    g_apart[(ms * 288 + j0 + ty + 16) * 64 + c0 + tx]      = a10;
    g_apart[(ms * 288 + j0 + ty + 16) * 64 + c0 + tx + 16] = a11;
}

// ---------------- Kernel C: softmax over c per row j ----------------
__global__ void k_softmax() {
    int j = blockIdx.x;
    int lane = threadIdx.x;
    float a1 = 0.f, a2 = 0.f;
    #pragma unroll
    for (int ms = 0; ms < 16; ms++) {
        a1 += g_apart[(ms * 288 + j) * 64 + lane];
        if (lane + 32 < Cn) a2 += g_apart[(ms * 288 + j) * 64 + lane + 32];
    }
    float e1 = expf(a1);
    float e2 = (lane + 32 < Cn) ? expf(a2) : 0.f;
    float s = e1 + e2;
    #pragma unroll
    for (int o = 16; o > 0; o >>= 1) s += __shfl_xor_sync(0xffffffffu, s, o);
    g_w[j * Cn + lane] = e1 / s;
    if (lane + 32 < Cn) g_w[j * Cn + lane + 32] = e2 / s;
}

// ---------------- Kernel D: pipelined mma.sync tf32 GEMM ----------------
// CTA: 96 j x 512 t (8 chunks of 64), double-buffered cp.async X; w loaded once.
// 3 CTAs/SM (24 warps). Warp tile: 48 j x 16 t (3 mt x 2 nt).
#define JT 96
#define WS2_STRIDE 36   // float2 units per jj row
#define XS_STRIDE 72    // floats; 72 mod 32 = 8 -> B-frag banks 8*tig+gid conflict-free
#define WS_OFF 0u                        // 96*36*8  = 27648 B
#define XB0_OFF 27648u                   // 64*72*4  = 18432 B
#define XB1_OFF (27648u + 18432u)
#define SM_TOTAL (27648u + 2u * 18432u)  // 64512 B -> 3 CTAs/SM

__global__ __launch_bounds__(256, 3) void k_main_v6(const float* __restrict__ X,
                                                    float* __restrict__ Y) {
    extern __shared__ __align__(16) char smem[];
    float2* ws2 = (float2*)(smem + WS_OFF);
    const uint32_t xb_u32[2] = { smem_u32(smem + XB0_OFF), smem_u32(smem + XB1_OFF) };
    const float* xbuf[2] = { (const float*)(smem + XB0_OFF), (const float*)(smem + XB1_OFF) };

    const int tid  = threadIdx.x;
    const int lane = tid & 31;
    const int warp = tid >> 5;
    const int gid  = lane >> 2;    // 0..7
    const int tig  = lane & 3;     // 0..3
    const int mw   = warp & 1;     // j half (48)
    const int nw   = warp >> 1;    // t quarter (16)

    const int jt = blockIdx.x;            // 0..2 fastest -> L2 reuse of X
    const int T0 = blockIdx.y * 512;      // CTA t origin
    const int b  = blockIdx.z;
    const int j0 = jt * JT;

    const float* Xb = X + (size_t)b * Cn * Tn + T0;

    // --- pad rows 60..63 of both X buffers (written once; persist across chunks) ---
    for (int q = tid; q < 4 * 16; q += 256) {
        int c = Cn + (q >> 4), t4 = q & 15;
        *(float4*)((char*)smem + XB0_OFF + (c * XS_STRIDE + t4 * 4) * 4) = make_float4(0.f, 0.f, 0.f, 0.f);
        *(float4*)((char*)smem + XB1_OFF + (c * XS_STRIDE + t4 * 4) * 4) = make_float4(0.f, 0.f, 0.f, 0.f);
    }

    // --- issue chunk 0 and 1 loads (60 rows x 16 float4 = 960 cp16 each) ---
    #pragma unroll
    for (int p = 0; p < 2; p++) {
        for (int q = tid; q < Cn * 16; q += 256) {
            int c = q >> 4, t4 = q & 15;
            cp16(xb_u32[p] + (uint32_t)(c * XS_STRIDE + t4 * 4) * 4u,
                 Xb + (size_t)c * Tn + p * 64 + t4 * 4);
        }
        CP_COMMIT();
    }

    // --- w tile -> ws2 (pair-packed, tf32-rna), zero-padded; overlaps cp.async flight ---
    for (int q = tid; q < JT * 32; q += 256) {
        int jj = q >> 5, idx = q & 31;          // idx = ks*4 + tg
        int ks = idx >> 2, tg = idx & 3;
        int k1 = ks * 8 + tg, k2 = k1 + 4;
        int j = j0 + jj;
        float v1 = (j < Jn && k1 < Cn) ? g_w[j * Cn + k1] : 0.f;
        float v2 = (j < Jn && k2 < Cn) ? g_w[j * Cn + k2] : 0.f;
        ws2[jj * WS2_STRIDE + idx] = make_float2(tf32_rna(v1), tf32_rna(v2));
    }

    const uint2* wsb2 = (const uint2*)ws2;

    #pragma unroll
    for (int p = 0; p < 8; p++) {
        if (p < 7) CP_WAIT(1); else CP_WAIT(0);
        __syncthreads();   // chunk p data + (p==0: ws2, pads) visible to all

        const uint32_t* xsb = (const uint32_t*)xbuf[p & 1];
        float acc[3][2][4] = {};

        #pragma unroll
        for (int ks = 0; ks < 8; ks++) {
            uint32_t a[3][4];
            #pragma unroll
            for (int mt = 0; mt < 3; mt++) {
                int jm = mw * 48 + mt * 16;
                uint2 pA = wsb2[(jm + gid)     * WS2_STRIDE + ks * 4 + tig];
                uint2 pB = wsb2[(jm + gid + 8) * WS2_STRIDE + ks * 4 + tig];
                a[mt][0] = pA.x; a[mt][2] = pA.y;
                a[mt][1] = pB.x; a[mt][3] = pB.y;
            }
            uint32_t bv[2][2];
            #pragma unroll
            for (int nt = 0; nt < 2; nt++) {
                int tcol = nw * 16 + nt * 8 + gid;
                bv[nt][0] = xsb[(ks * 8 + tig)     * XS_STRIDE + tcol];
                bv[nt][1] = xsb[(ks * 8 + tig + 4) * XS_STRIDE + tcol];
            }
            #pragma unroll
            for (int mt = 0; mt < 3; mt++)
                #pragma unroll
                for (int nt = 0; nt < 2; nt++)
                    mma8(acc[mt][nt], a[mt], bv[nt]);
        }

        // release buffer and issue next load BEFORE the stores
        if (p < 6) {
            __syncthreads();   // all warps done reading buf[p&1]
            for (int q = tid; q < Cn * 16; q += 256) {
                int c = q >> 4, t4 = q & 15;
                cp16(xb_u32[p & 1] + (uint32_t)(c * XS_STRIDE + t4 * 4) * 4u,
                     Xb + (size_t)c * Tn + (p + 2) * 64 + t4 * 4);
            }
            CP_COMMIT();
        }

        // --- stores for chunk p ---
        #pragma unroll
        for (int mt = 0; mt < 3; mt++) {
            int j = j0 + mw * 48 + mt * 16 + gid;
            #pragma unroll
            for (int nt = 0; nt < 2; nt++) {
                int t = T0 + p * 64 + nw * 16 + nt * 8 + tig * 2;
                float* base = Y + ((size_t)b * Jn + j) * Tn + t;
                if (j < Jn)
                    *(float2*)base = make_float2(acc[mt][nt][0], acc[mt][nt][1]);
                if (j + 8 < Jn)
                    *(float2*)(base + 8 * (size_t)Tn) = make_float2(acc[mt][nt][2], acc[mt][nt][3]);
            }
        }
    }
}

// ---------------- launch ----------------
extern "C" void kernel_launch(void* const* d_in, const int* in_sizes, int n_in,
                              void* d_out, int out_size) {
    const float* X = nullptr; const float* z_re = nullptr;
    const float* z_im = nullptr; const float* loc = nullptr;
    for (int i = 0; i < n_in; i++) {
        int s = in_sizes[i];
        if (s == Bn * Cn * Tn)      X = (const float*)d_in[i];
        else if (s == Cn * 2)       loc = (const float*)d_in[i];
        else if (s == Jn * MMn) {
            if (!z_re) z_re = (const float*)d_in[i];
            else       z_im = (const float*)d_in[i];
        }
    }
    float* Y = (float*)d_out;

    (void)cudaFuncSetAttribute(k_main_v6, cudaFuncAttributeMaxDynamicSharedMemorySize, SM_TOTAL);

    k_tables<<<Cn, 256>>>(loc);
    k_logits<<<dim3(9, 2, 16), 256>>>(z_re, z_im);
    k_softmax<<<Jn, 32>>>();
    k_main_v6<<<dim3(3, Tn / 512, Bn), 256, SM_TOTAL>>>(X, Y);
}

// round 16
// speedup vs baseline: 1.1304x; 1.1304x over previous
#include <cuda_runtime.h>
#include <math.h>
#include <stdint.h>

// Problem constants
#define Bn 64
#define Cn 60
#define Tn 4096
#define Jn 270
#define MMn 1024   // K*K = 32*32

// ---------------- device scratch ----------------
__device__ float g_cs[Cn * MMn];         // cos table [c][m]
__device__ float g_sn[Cn * MMn];         // sin table [c][m]
__device__ float g_apart[16 * 288 * 64]; // logit partials [ms][j(288)][c(64)]
__device__ float g_w[Jn * Cn];           // softmax weights [j][c]

__device__ __forceinline__ float tf32_rna(float v) {
    float r; asm("cvt.rna.tf32.f32 %0, %1;" : "=f"(r) : "f"(v)); return r;
}
__device__ __forceinline__ uint32_t smem_u32(const void* p) {
    uint32_t a;
    asm("{ .reg .u64 t; cvta.to.shared.u64 t, %1; cvt.u32.u64 %0, t; }" : "=r"(a) : "l"(p));
    return a;
}
__device__ __forceinline__ void cp16(uint32_t dst, const void* src) {
    asm volatile("cp.async.cg.shared.global [%0], [%1], 16;" :: "r"(dst), "l"(src));
}
#define CP_COMMIT() asm volatile("cp.async.commit_group;" ::: "memory")
#define CP_WAIT(n)  asm volatile("cp.async.wait_group %0;" :: "n"(n) : "memory")

// m16n8k8 tf32 mma: D += A(row,16x8) * B(col,8x8)
__device__ __forceinline__ void mma8(float* d, const uint32_t* a, const uint32_t* b) {
    asm volatile(
        "mma.sync.aligned.m16n8k8.row.col.f32.tf32.tf32.f32 "
        "{%0,%1,%2,%3}, {%4,%5,%6,%7}, {%8,%9}, {%0,%1,%2,%3};"
        : "+f"(d[0]), "+f"(d[1]), "+f"(d[2]), "+f"(d[3])
        : "r"(a[0]), "r"(a[1]), "r"(a[2]), "r"(a[3]), "r"(b[0]), "r"(b[1]));
}

// ---------------- Kernel A: trig tables ----------------
__global__ void k_tables(const float* __restrict__ loc) {
    int c = blockIdx.x;
    float x = loc[c * 2 + 0];
    float y = loc[c * 2 + 1];
    for (int m = threadIdx.x; m < MMn; m += blockDim.x) {
        int k = m >> 5, l = m & 31;
        float r = (float)k * x + (float)l * y;
        r -= rintf(r);
        float s, cv;
        sincospif(2.0f * r, &s, &cv);
        g_cs[c * MMn + m] = cv;
        g_sn[c * MMn + m] = s;
    }
}

// ---------------- Kernel B: logits GEMM (16 m-splits, single 64-m pass) ----------------
__global__ __launch_bounds__(256) void k_logits16(const float* __restrict__ z_re,
                                                  const float* __restrict__ z_im) {
    __shared__ float zr[32][65], zi[32][65], tc[32][65], ts[32][65];
    int j0 = blockIdx.x * 32;
    int c0 = blockIdx.y * 32;
    int m0 = blockIdx.z * 64;
    int tid = threadIdx.x;
    int tx = tid & 15, ty = tid >> 4;

    for (int i = tid; i < 2048; i += 256) {
        int rr = i >> 6, mm = i & 63;
        int gm = m0 + mm;
        int j = j0 + rr;
        float vr = 0.f, vi = 0.f;
        if (j < Jn) { vr = z_re[j * MMn + gm]; vi = z_im[j * MMn + gm]; }
        zr[rr][mm] = vr; zi[rr][mm] = vi;
        int c = c0 + rr;
        float vc = 0.f, vs = 0.f;
        if (c < Cn) { vc = g_cs[c * MMn + gm]; vs = g_sn[c * MMn + gm]; }
        tc[rr][mm] = vc; ts[rr][mm] = vs;
    }
    __syncthreads();

    float a00 = 0.f, a01 = 0.f, a10 = 0.f, a11 = 0.f;
    #pragma unroll 16
    for (int mm = 0; mm < 64; mm++) {
        float r0 = zr[ty][mm],      r1 = zr[ty + 16][mm];
        float i0 = zi[ty][mm],      i1 = zi[ty + 16][mm];
        float c0v = tc[tx][mm],     c1v = tc[tx + 16][mm];
        float s0v = ts[tx][mm],     s1v = ts[tx + 16][mm];
        a00 += r0 * c0v + i0 * s0v;
        a01 += r0 * c1v + i0 * s1v;
        a10 += r1 * c0v + i1 * s0v;
        a11 += r1 * c1v + i1 * s1v;
    }
    int ms = blockIdx.z;
    g_apart[(ms * 288 + j0 + ty)      * 64 + c0 + tx]      = a00;
    g_apart[(ms * 288 + j0 + ty)      * 64 + c0 + tx + 16] = a01;
    g_apart[(ms * 288 + j0 + ty + 16) * 64 + c0 + tx]      = a10;
    g_apart[(ms * 288 + j0 + ty + 16) * 64 + c0 + tx + 16] = a11;
}

// ---------------- Kernel C: softmax over c per row j ----------------
__global__ void k_softmax() {
    int j = blockIdx.x;
    int lane = threadIdx.x;
    float a1 = 0.f, a2 = 0.f;
    #pragma unroll
    for (int ms = 0; ms < 16; ms++) {
        a1 += g_apart[(ms * 288 + j) * 64 + lane];
        if (lane + 32 < Cn) a2 += g_apart[(ms * 288 + j) * 64 + lane + 32];
    }
    float e1 = expf(a1);
    float e2 = (lane + 32 < Cn) ? expf(a2) : 0.f;
    float s = e1 + e2;
    #pragma unroll
    for (int o = 16; o > 0; o >>= 1) s += __shfl_xor_sync(0xffffffffu, s, o);
    g_w[j * Cn + lane] = e1 / s;
    if (lane + 32 < Cn) g_w[j * Cn + lane + 32] = e2 / s;
}

// ---------------- Kernel D: pipelined mma.sync tf32 GEMM (R10 v4 design) ----------------
// CTA: 96 j x 512 t (4 chunks of 128), double-buffered cp.async X; w loaded once.
#define JT 96
#define WS_STRIDE 68    // floats; A-frag banks conflict-free
#define XS_STRIDE 136   // floats; B-frag banks conflict-free; row = 544 B (16B-aligned)
#define WS_OFF 0u                        // 96*68*4  = 26112 B
#define XB0_OFF 26112u                   // 64*136*4 = 34816 B
#define XB1_OFF (26112u + 34816u)
#define SM_TOTAL (26112u + 2u * 34816u)  // 95744 B -> 2 CTAs/SM

__global__ __launch_bounds__(256, 2) void k_main_v7(const float* __restrict__ X,
                                                    float* __restrict__ Y) {
    extern __shared__ __align__(16) char smem[];
    float* ws = (float*)(smem + WS_OFF);
    const uint32_t xb_u32[2] = { smem_u32(smem + XB0_OFF), smem_u32(smem + XB1_OFF) };
    const float* xbuf[2] = { (const float*)(smem + XB0_OFF), (const float*)(smem + XB1_OFF) };

    const int tid  = threadIdx.x;
    const int lane = tid & 31;
    const int warp = tid >> 5;
    const int gid  = lane >> 2;    // 0..7
    const int tig  = lane & 3;     // 0..3
    const int mw   = warp & 1;     // j half (48)
    const int nw   = warp >> 1;    // t quarter (32)

    const int jt = blockIdx.x;            // 0..2 fastest -> L2 reuse of X
    const int T0 = blockIdx.y * 512;      // CTA t origin
    const int b  = blockIdx.z;
    const int j0 = jt * JT;

    const float* Xb = X + (size_t)b * Cn * Tn + T0;

    // --- pad rows 60..63 of both X buffers (written once; persist across chunks) ---
    for (int q = tid; q < 4 * 32; q += 256) {
        int c = Cn + (q >> 5), t4 = q & 31;
        *(float4*)((char*)smem + XB0_OFF + (c * XS_STRIDE + t4 * 4) * 4) = make_float4(0.f, 0.f, 0.f, 0.f);
        *(float4*)((char*)smem + XB1_OFF + (c * XS_STRIDE + t4 * 4) * 4) = make_float4(0.f, 0.f, 0.f, 0.f);
    }

    // --- issue chunk 0 and 1 loads ---
    #pragma unroll
    for (int p = 0; p < 2; p++) {
        for (int q = tid; q < Cn * 32; q += 256) {
            int c = q >> 5, t4 = q & 31;
            cp16(xb_u32[p] + (uint32_t)(c * XS_STRIDE + t4 * 4) * 4u,
                 Xb + (size_t)c * Tn + p * 128 + t4 * 4);
        }
        CP_COMMIT();
    }

    // --- w tile -> ws (tf32-rna), zero-padded; overlaps with cp.async flight ---
    for (int q = tid; q < JT * 64; q += 256) {
        int jj = q >> 6, c = q & 63;
        int j = j0 + jj;
        float v = (j < Jn && c < Cn) ? g_w[j * Cn + c] : 0.f;
        ws[jj * WS_STRIDE + c] = tf32_rna(v);
    }

    const uint32_t* wsb = (const uint32_t*)ws;

    #pragma unroll
    for (int p = 0; p < 4; p++) {
        if (p < 3) CP_WAIT(1); else CP_WAIT(0);
        __syncthreads();   // chunk p data + (p==0: ws, pads) visible to all

        const uint32_t* xsb = (const uint32_t*)xbuf[p & 1];
        float acc[3][4][4] = {};

        #pragma unroll
        for (int k0 = 0; k0 < 64; k0 += 8) {
            uint32_t a[3][4];
            #pragma unroll
            for (int mt = 0; mt < 3; mt++) {
                int jm = mw * 48 + mt * 16;
                a[mt][0] = wsb[(jm + gid)     * WS_STRIDE + k0 + tig];
                a[mt][1] = wsb[(jm + gid + 8) * WS_STRIDE + k0 + tig];
                a[mt][2] = wsb[(jm + gid)     * WS_STRIDE + k0 + tig + 4];
                a[mt][3] = wsb[(jm + gid + 8) * WS_STRIDE + k0 + tig + 4];
            }
            uint32_t bv[4][2];
            #pragma unroll
            for (int nt = 0; nt < 4; nt++) {
                int tcol = nw * 32 + nt * 8 + gid;
                bv[nt][0] = xsb[(k0 + tig)     * XS_STRIDE + tcol];
                bv[nt][1] = xsb[(k0 + tig + 4) * XS_STRIDE + tcol];
            }
            #pragma unroll
            for (int mt = 0; mt < 3; mt++)
                #pragma unroll
                for (int nt = 0; nt < 4; nt++)
                    mma8(acc[mt][nt], a[mt], bv[nt]);
        }

        // --- stores for chunk p (issue immediately per-warp, then barrier) ---
        #pragma unroll
        for (int mt = 0; mt < 3; mt++) {
            int j = j0 + mw * 48 + mt * 16 + gid;
            #pragma unroll
            for (int nt = 0; nt < 4; nt++) {
                int t = T0 + p * 128 + nw * 32 + nt * 8 + tig * 2;
                float* base = Y + ((size_t)b * Jn + j) * Tn + t;
                if (j < Jn)
                    *(float2*)base = make_float2(acc[mt][nt][0], acc[mt][nt][1]);
                if (j + 8 < Jn)
                    *(float2*)(base + 8 * (size_t)Tn) = make_float2(acc[mt][nt][2], acc[mt][nt][3]);
            }
        }

        __syncthreads();   // all reads of buf[p&1] done before overwrite
        if (p < 2) {
            for (int q = tid; q < Cn * 32; q += 256) {
                int c = q >> 5, t4 = q & 31;
                cp16(xb_u32[p & 1] + (uint32_t)(c * XS_STRIDE + t4 * 4) * 4u,
                     Xb + (size_t)c * Tn + (p + 2) * 128 + t4 * 4);
            }
            CP_COMMIT();
        }
    }
}

// ---------------- launch ----------------
extern "C" void kernel_launch(void* const* d_in, const int* in_sizes, int n_in,
                              void* d_out, int out_size) {
    const float* X = nullptr; const float* z_re = nullptr;
    const float* z_im = nullptr; const float* loc = nullptr;
    for (int i = 0; i < n_in; i++) {
        int s = in_sizes[i];
        if (s == Bn * Cn * Tn)      X = (const float*)d_in[i];
        else if (s == Cn * 2)       loc = (const float*)d_in[i];
        else if (s == Jn * MMn) {
            if (!z_re) z_re = (const float*)d_in[i];
            else       z_im = (const float*)d_in[i];
        }
    }
    float* Y = (float*)d_out;

    (void)cudaFuncSetAttribute(k_main_v7, cudaFuncAttributeMaxDynamicSharedMemorySize, SM_TOTAL);

    k_tables<<<Cn, 256>>>(loc);
    k_logits16<<<dim3(9, 2, 16), 256>>>(z_re, z_im);
    k_softmax<<<Jn, 32>>>();
    k_main_v7<<<dim3(3, Tn / 512, Bn), 256, SM_TOTAL>>>(X, Y);
}